// round 1
// baseline (speedup 1.0000x reference)
#include <cuda_runtime.h>
#include <cstdint>
#include <math.h>

// ---------------- problem constants ----------------
#define NTOK    32768          // B*T = 8*4096
#define NEXP    16
#define LINP    1792           // packed features (32 city features folded into bias)
#define KC      64             // feature chunk
#define NCHUNK  28             // 1792/64
#define TPB     128            // threads per block
#define TOKBLK  128            // tokens per block
#define NBLK    (NTOK / TOKBLK)

#define RO_OFF  0
#define IDX_OFF (NTOK * NEXP)            // 524288
#define G1_OFF  (IDX_OFF + NTOK * 2)     // 589824

// packed weights: pair e = (w_route[f][e], w_noise[f][e]); city rows removed
__device__ float2 g_wpack[LINP * NEXP];
__device__ float2 g_bias[NEXP];          // bias + city·W_city contribution

// ---------------- f32x2 helpers ----------------
__device__ __forceinline__ void fma2(unsigned long long& acc,
                                     unsigned long long x,
                                     unsigned long long w) {
    asm("fma.rn.f32x2 %0, %1, %2, %0;" : "+l"(acc) : "l"(x), "l"(w));
}
__device__ __forceinline__ unsigned long long pack2(float v) {
    unsigned long long r;
    asm("mov.b64 %0, {%1, %1};" : "=l"(r) : "f"(v));
    return r;
}
__device__ __forceinline__ float2 unpack2(unsigned long long a) {
    float2 r;
    asm("mov.b64 {%0, %1}, %2;" : "=f"(r.x), "=f"(r.y) : "l"(a));
    return r;
}
__device__ __forceinline__ float softplus_f(float x) {
    // log1p(exp(x)) stable form == jax.nn.softplus
    return fmaxf(x, 0.f) + log1pf(expf(-fabsf(x)));
}

// ---------------- prep: pack weights, fold city into bias ----------------
__global__ void prep_kernel(const float* __restrict__ w_route,
                            const float* __restrict__ b_route,
                            const float* __restrict__ w_noise,
                            const float* __restrict__ b_noise,
                            const float* __restrict__ city_emb,
                            const int*   __restrict__ city_index)
{
    int idx = blockIdx.x * blockDim.x + threadIdx.x;
    if (idx < LINP * NEXP) {
        int pf = idx >> 4, e = idx & 15;
        int g = pf + (pf >= 1024 ? 32 : 0);   // skip city rows [1024,1056)
        g_wpack[idx] = make_float2(w_route[g * 16 + e], w_noise[g * 16 + e]);
    }
    if (idx < NEXP) {
        int ci = city_index[0];
        float br = b_route[idx], bn = b_noise[idx];
        #pragma unroll
        for (int j = 0; j < 32; j++) {
            float cv = city_emb[ci * 32 + j];
            br = fmaf(cv, w_route[(1024 + j) * 16 + idx], br);
            bn = fmaf(cv, w_noise[(1024 + j) * 16 + idx], bn);
        }
        g_bias[idx] = make_float2(br, bn);
    }
}

// ---------------- main fused kernel ----------------
__global__ __launch_bounds__(TPB, 2)
void router_main(const float* __restrict__ mh,
                 const float* __restrict__ dt,
                 const float* __restrict__ dd,
                 const float* __restrict__ drg,
                 const float* __restrict__ dent,
                 const float* __restrict__ eps,
                 float* __restrict__ out,
                 int out_size)
{
    // Xs: transposed [feat][token], 64x128 fp32, XOR-swizzled at 4-token grain
    __shared__ __align__(16) float  Xs[KC * 128];
    __shared__ __align__(16) float2 Ws[KC][NEXP];

    const int tid = threadIdx.x;
    const int og  = tid >> 5;     // warp id == output-pair group (4 f32x2 pairs)
    const int tg  = tid & 31;     // token group: tokens 4*tg .. 4*tg+3
    const int tb  = blockIdx.x * TOKBLK;

    // accumulators: acc[token][pair] holds (route_logit, noise_logit) packed f32x2
    unsigned long long acc[4][4];
    #pragma unroll
    for (int j = 0; j < 4; j++) {
        unsigned long long b =
            *reinterpret_cast<const unsigned long long*>(&g_bias[og * 4 + j]);
        #pragma unroll
        for (int i = 0; i < 4; i++) acc[i][j] = b;
    }

    const int ldtok = tid >> 4;        // 0..7  (token sub-index per load round)
    const int ldm   = tid & 15;        // feature-float4 index
    const int f0    = ldm * 4;
    const int sig4  = 4 * (ldm & 7);   // swizzle for store side

    float4 xr[16];
    float4 wr[4];

    // per-chunk source resolution + register prefetch
    auto prefetch = [&](int c) {
        const float* src; int colbase, stride;
        if (c < 16)      { src = mh;   colbase = c * 64;        stride = 1024; }
        else if (c < 20) { src = dt;   colbase = (c - 16) * 64; stride = 256;  }
        else if (c < 24) { src = dd;   colbase = (c - 20) * 64; stride = 256;  }
        else if (c < 26) { src = drg;  colbase = (c - 24) * 64; stride = 128;  }
        else             { src = dent; colbase = (c - 26) * 64; stride = 128;  }
        #pragma unroll
        for (int q = 0; q < 16; q++) {
            int tl = ldtok + 8 * q;
            xr[q] = *reinterpret_cast<const float4*>(
                src + (size_t)(tb + tl) * stride + colbase + f0);
        }
        const float4* wp = reinterpret_cast<const float4*>(&g_wpack[c * 64 * NEXP]);
        #pragma unroll
        for (int r = 0; r < 4; r++) wr[r] = wp[r * 128 + tid];
    };

    prefetch(0);

    for (int c = 0; c < NCHUNK; c++) {
        __syncthreads();   // previous chunk fully consumed
        // store staged tile (transpose + swizzle)
        #pragma unroll
        for (int q = 0; q < 16; q++) {
            int tl2 = (ldtok + 8 * q) ^ sig4;
            Xs[(f0 + 0) * 128 + tl2] = xr[q].x;
            Xs[(f0 + 1) * 128 + tl2] = xr[q].y;
            Xs[(f0 + 2) * 128 + tl2] = xr[q].z;
            Xs[(f0 + 3) * 128 + tl2] = xr[q].w;
        }
        #pragma unroll
        for (int r = 0; r < 4; r++)
            reinterpret_cast<float4*>(Ws)[r * 128 + tid] = wr[r];
        __syncthreads();

        if (c + 1 < NCHUNK) prefetch(c + 1);   // LDG latency hidden by compute

        #pragma unroll 16
        for (int f = 0; f < KC; f++) {
            const float4 xv = *reinterpret_cast<const float4*>(
                &Xs[f * 128 + ((4 * tg) ^ (4 * ((f >> 2) & 7)))]);
            const ulonglong2 wA =
                *reinterpret_cast<const ulonglong2*>(&Ws[f][og * 4]);
            const ulonglong2 wB =
                *reinterpret_cast<const ulonglong2*>(&Ws[f][og * 4 + 2]);
            unsigned long long xx;
            xx = pack2(xv.x);
            fma2(acc[0][0], xx, wA.x); fma2(acc[0][1], xx, wA.y);
            fma2(acc[0][2], xx, wB.x); fma2(acc[0][3], xx, wB.y);
            xx = pack2(xv.y);
            fma2(acc[1][0], xx, wA.x); fma2(acc[1][1], xx, wA.y);
            fma2(acc[1][2], xx, wB.x); fma2(acc[1][3], xx, wB.y);
            xx = pack2(xv.z);
            fma2(acc[2][0], xx, wA.x); fma2(acc[2][1], xx, wA.y);
            fma2(acc[2][2], xx, wB.x); fma2(acc[2][3], xx, wB.y);
            xx = pack2(xv.w);
            fma2(acc[3][0], xx, wA.x); fma2(acc[3][1], xx, wA.y);
            fma2(acc[3][2], xx, wB.x); fma2(acc[3][3], xx, wB.y);
        }
    }

    // ---------------- exchange logits + fused epilogue ----------------
    __syncthreads();   // all compute reads of Xs finished
    float2* sml = reinterpret_cast<float2*>(Xs);   // [128][17] padded
    #pragma unroll
    for (int i = 0; i < 4; i++)
        #pragma unroll
        for (int j = 0; j < 4; j++)
            sml[(tg * 4 + i) * 17 + (og * 4 + j)] = unpack2(acc[i][j]);
    __syncthreads();

    const int t = tb + tid;   // one token per thread
    float nz[16];
    {
        float4 ev[4];
        const float4* ep = reinterpret_cast<const float4*>(eps + (size_t)t * 16);
        ev[0] = ep[0]; ev[1] = ep[1]; ev[2] = ep[2]; ev[3] = ep[3];
        const float* ef = reinterpret_cast<const float*>(ev);
        #pragma unroll
        for (int e = 0; e < 16; e++) {
            float2 l = sml[tid * 17 + e];
            nz[e] = l.x + ef[e] * softplus_f(l.y);
        }
    }

    // dense softmax (gate1)
    float m = nz[0];
    #pragma unroll
    for (int e = 1; e < 16; e++) m = fmaxf(m, nz[e]);
    float ex[16], s = 0.f;
    #pragma unroll
    for (int e = 0; e < 16; e++) { ex[e] = expf(nz[e] - m); s += ex[e]; }
    float inv = 1.f / s;

    // top-2 (first-occurrence ties, matches lax.top_k)
    int i1 = 0; float v1 = nz[0];
    #pragma unroll
    for (int e = 1; e < 16; e++) if (nz[e] > v1) { v1 = nz[e]; i1 = e; }
    int i2 = -1; float v2 = -INFINITY;
    #pragma unroll
    for (int e = 0; e < 16; e++) if (e != i1 && nz[e] > v2) { v2 = nz[e]; i2 = e; }

    float t2 = expf(v2 - v1);          // v2 <= v1, stable
    float r1 = 1.f / (1.f + t2);
    float r2 = t2 * r1;

    // router_output (sparse softmax)
    {
        float ro[16];
        #pragma unroll
        for (int e = 0; e < 16; e++)
            ro[e] = (e == i1) ? r1 : ((e == i2) ? r2 : 0.f);
        float4* op = reinterpret_cast<float4*>(out + RO_OFF + (size_t)t * 16);
        op[0] = make_float4(ro[0],  ro[1],  ro[2],  ro[3]);
        op[1] = make_float4(ro[4],  ro[5],  ro[6],  ro[7]);
        op[2] = make_float4(ro[8],  ro[9],  ro[10], ro[11]);
        op[3] = make_float4(ro[12], ro[13], ro[14], ro[15]);
    }
    // indices (as float)
    if (out_size >= IDX_OFF + NTOK * 2) {
        float2* ip = reinterpret_cast<float2*>(out + IDX_OFF + (size_t)t * 2);
        ip[0] = make_float2((float)i1, (float)i2);
    }
    // gate1
    if (out_size >= G1_OFF + NTOK * NEXP) {
        float g[16];
        #pragma unroll
        for (int e = 0; e < 16; e++) g[e] = ex[e] * inv;
        float4* gp = reinterpret_cast<float4*>(out + G1_OFF + (size_t)t * 16);
        gp[0] = make_float4(g[0],  g[1],  g[2],  g[3]);
        gp[1] = make_float4(g[4],  g[5],  g[6],  g[7]);
        gp[2] = make_float4(g[8],  g[9],  g[10], g[11]);
        gp[3] = make_float4(g[12], g[13], g[14], g[15]);
    }
}

// ---------------- launch ----------------
extern "C" void kernel_launch(void* const* d_in, const int* in_sizes, int n_in,
                              void* d_out, int out_size)
{
    const float* mh      = (const float*)d_in[0];
    const float* dt      = (const float*)d_in[1];
    const float* dd      = (const float*)d_in[2];
    const float* drg     = (const float*)d_in[3];
    const float* dent    = (const float*)d_in[4];
    const float* city    = (const float*)d_in[5];
    const float* w_route = (const float*)d_in[6];
    const float* b_route = (const float*)d_in[7];
    const float* w_noise = (const float*)d_in[8];
    const float* b_noise = (const float*)d_in[9];
    const float* eps     = (const float*)d_in[10];
    const int*   ci      = (const int*)d_in[11];

    prep_kernel<<<(LINP * NEXP + 255) / 256, 256>>>(w_route, b_route,
                                                    w_noise, b_noise, city, ci);
    router_main<<<NBLK, TPB>>>(mh, dt, dd, drg, dent, eps,
                               (float*)d_out, out_size);
}